// round 7
// baseline (speedup 1.0000x reference)
#include <cuda_runtime.h>
#include <cstdint>

#define NUM_CLASSES 601
#define OUT_DIM     27
#define ROW_PAD     28                     // padded floats per row = 112 B (16B-aligned)
#define ROWS_PER_BLOCK 128
#define THREADS     256

// Padded softmax table: 601 rows x 7 float4 (112 B each) = ~66 KB, L1-resident.
__device__ float4 g_tab4[NUM_CLASSES * (ROW_PAD / 4)];

// One block per class row; lane j computes exp, warp-reduce, write padded row.
__global__ void build_probs_kernel(const float* __restrict__ W) {
    int r = blockIdx.x;
    int l = threadIdx.x;
    float e = 0.0f;
    if (l < OUT_DIM) e = expf(W[r * OUT_DIM + l]);
    float s = e;
    #pragma unroll
    for (int o = 16; o; o >>= 1) s += __shfl_xor_sync(0xffffffffu, s, o);
    float* tab = (float*)g_tab4;
    if (l < ROW_PAD) tab[r * ROW_PAD + l] = (l < OUT_DIM) ? (e / s) : 0.0f;
}

// Each block: 128 rows. Thread pair (2 threads) fetches one padded table row via
// LDG.128, packs 27 floats into smem (contiguous, no padding), then one thread
// issues a single bulk-async copy smem -> gmem (13824 B, contiguous, aligned).
__global__ void __launch_bounds__(THREADS) gather_kernel(const int* __restrict__ idx,
                                                         float* __restrict__ out,
                                                         int nrows) {
    __shared__ float stage[ROWS_PER_BLOCK * OUT_DIM];   // 13824 B

    int row0 = blockIdx.x * ROWS_PER_BLOCK;
    int t    = threadIdx.x;
    int j    = t >> 1;          // local row 0..127
    int half = t & 1;           // 0: floats 0..15, 1: floats 16..26
    int row  = row0 + j;

    if (row < nrows) {
        int b = __ldg(&idx[row]);                       // pairs broadcast
        const float4* __restrict__ rp = &g_tab4[b * (ROW_PAD / 4)];
        float* dst = &stage[j * OUT_DIM];
        if (half == 0) {
            float4 a = __ldg(rp + 0);
            float4 c = __ldg(rp + 1);
            float4 d = __ldg(rp + 2);
            float4 e = __ldg(rp + 3);
            dst[0]  = a.x; dst[1]  = a.y; dst[2]  = a.z; dst[3]  = a.w;
            dst[4]  = c.x; dst[5]  = c.y; dst[6]  = c.z; dst[7]  = c.w;
            dst[8]  = d.x; dst[9]  = d.y; dst[10] = d.z; dst[11] = d.w;
            dst[12] = e.x; dst[13] = e.y; dst[14] = e.z; dst[15] = e.w;
        } else {
            float4 a = __ldg(rp + 4);
            float4 c = __ldg(rp + 5);
            float4 d = __ldg(rp + 6);
            dst[16] = a.x; dst[17] = a.y; dst[18] = a.z; dst[19] = a.w;
            dst[20] = c.x; dst[21] = c.y; dst[22] = c.z; dst[23] = c.w;
            dst[24] = d.x; dst[25] = d.y; dst[26] = d.z;   // d.w is row pad
        }
    }
    __syncthreads();

    if (t == 0) {
        int rows_this = nrows - row0;
        if (rows_this > ROWS_PER_BLOCK) rows_this = ROWS_PER_BLOCK;
        unsigned bytes = (unsigned)(rows_this * OUT_DIM * (int)sizeof(float));
        // bytes = 13824 for full blocks (BATCH % 128 == 0): multiple of 16, aligned.
        uint32_t saddr = (uint32_t)__cvta_generic_to_shared(stage);
        float* gdst = out + (size_t)row0 * OUT_DIM;
        asm volatile("fence.proxy.async.shared::cta;" ::: "memory");
        asm volatile(
            "cp.async.bulk.global.shared::cta.bulk_group [%0], [%1], %2;"
            :: "l"(gdst), "r"(saddr), "r"(bytes) : "memory");
        asm volatile("cp.async.bulk.commit_group;" ::: "memory");
        asm volatile("cp.async.bulk.wait_group 0;" ::: "memory");
    }
}

extern "C" void kernel_launch(void* const* d_in, const int* in_sizes, int n_in,
                              void* d_out, int out_size) {
    // Inputs: bigram_idx (int32, BATCH), W (float32, 601*27). Identify W by size.
    const int*   idx = (const int*)d_in[0];
    const float* W   = (const float*)d_in[1];
    int idx_n = in_sizes[0];
    if (n_in >= 2 && in_sizes[0] == NUM_CLASSES * OUT_DIM) {
        W     = (const float*)d_in[0];
        idx   = (const int*)d_in[1];
        idx_n = in_sizes[1];
    }
    float* out = (float*)d_out;

    // 1) 601-row softmax table (tiny, ~3 us).
    build_probs_kernel<<<NUM_CLASSES, 32>>>(W);

    // 2) Row-granular gather + pack + TMA bulk store.
    int blocks = (idx_n + ROWS_PER_BLOCK - 1) / ROWS_PER_BLOCK;
    gather_kernel<<<blocks, THREADS>>>(idx, out, idx_n);
}

// round 11
// speedup vs baseline: 1.5505x; 1.5505x over previous
#include <cuda_runtime.h>
#include <cstdint>

#define NUM_CLASSES 601
#define OUT_DIM     27
#define TAB_ELEMS   (NUM_CLASSES * OUT_DIM)            // 16227 floats = 64908 B
#define TAB_F4      ((TAB_ELEMS + 3) / 4)              // 4057 float4
#define GATHER_BLOCKS  444                             // 3 per SM (148 SMs)
#define GATHER_THREADS 512
#define SMEM_BYTES  (TAB_F4 * 16)                      // 64912 B dynamic smem

// Softmax table in global (padded to float4 multiple for vector copy).
__device__ float4 g_tab4[TAB_F4];

// One block per class row; lane j computes exp, warp-reduce, write row (stride 27).
__global__ void build_probs_kernel(const float* __restrict__ W) {
    int r = blockIdx.x;
    int l = threadIdx.x;
    float e = 0.0f;
    if (l < OUT_DIM) e = expf(W[r * OUT_DIM + l]);
    float s = e;
    #pragma unroll
    for (int o = 16; o; o >>= 1) s += __shfl_xor_sync(0xffffffffu, s, o);
    float* tab = (float*)g_tab4;
    if (l < OUT_DIM) tab[r * OUT_DIM + l] = e / s;
}

// Grid-stride gather. Table lives in dynamic smem (stride-27 rows: 27 odd =>
// bank-uniform row starts). Warp handles 128 consecutive flat floats per
// iteration; lane l does flat = base + 32k + l => LDS reads <=3 contiguous
// segments (conflict ~2), STG.32 perfectly coalesced, idx loads L1-hot.
__global__ void __launch_bounds__(GATHER_THREADS) gather_kernel(
        const int* __restrict__ idx, float* __restrict__ out, unsigned n) {
    extern __shared__ float s_tab[];

    // Cooperative vectorized table copy into smem.
    {
        const float4* __restrict__ src = g_tab4;
        float4* dst = (float4*)s_tab;
        for (int i = threadIdx.x; i < TAB_F4; i += GATHER_THREADS)
            dst[i] = src[i];
    }
    __syncthreads();

    const unsigned warps_per_block = GATHER_THREADS >> 5;
    const unsigned gwarp  = blockIdx.x * warps_per_block + (threadIdx.x >> 5);
    const unsigned nwarps = gridDim.x * warps_per_block;
    const unsigned lane   = threadIdx.x & 31u;
    const unsigned stride = nwarps * 128u;

    for (unsigned base = gwarp * 128u; base < n; base += stride) {
        #pragma unroll
        for (int k = 0; k < 4; k++) {
            unsigned f = base + (unsigned)(k * 32) + lane;
            if (f < n) {
                unsigned row = f / 27u;              // magic-multiply
                unsigned col = f - row * 27u;
                int b = __ldg(&idx[row]);            // <=2 words per warp, L1-hot
                __stcs(&out[f], s_tab[(unsigned)b * 27u + col]);
            }
        }
    }
}

extern "C" void kernel_launch(void* const* d_in, const int* in_sizes, int n_in,
                              void* d_out, int out_size) {
    // Inputs: bigram_idx (int32, BATCH), W (float32, 601*27). Identify W by size.
    const int*   idx = (const int*)d_in[0];
    const float* W   = (const float*)d_in[1];
    if (n_in >= 2 && in_sizes[0] == TAB_ELEMS) {
        W   = (const float*)d_in[0];
        idx = (const int*)d_in[1];
    }
    float* out = (float*)d_out;

    // Allow >48KB dynamic smem (idempotent; host-side, not a stream op).
    static int attr_done = 0;
    if (!attr_done) {
        cudaFuncSetAttribute(gather_kernel,
                             cudaFuncAttributeMaxDynamicSharedMemorySize,
                             SMEM_BYTES);
        attr_done = 1;
    }

    // 1) 601-row softmax table.
    build_probs_kernel<<<NUM_CLASSES, 32>>>(W);

    // 2) smem-table gather, grid-stride over the flat output.
    gather_kernel<<<GATHER_BLOCKS, GATHER_THREADS, SMEM_BYTES>>>(
        idx, out, (unsigned)out_size);
}